// round 13
// baseline (speedup 1.0000x reference)
#include <cuda_runtime.h>
#include <stdint.h>

typedef unsigned int u32;

#define M_TOT 4096
#define K1    4096
#define N1    11008
#define N2    4096
#define SROW  68                    // floats per smem row: 64 + 4 pad (stride 272B, conflict-free)
#define STAGE (128 * SROW)          // floats per stage per array (34816 B)

// scratch: tf32-rounded x; h = silu(g)*u stored tf32-rounded
__device__ float g_xr[(size_t)M_TOT * K1];
__device__ float g_h [(size_t)M_TOT * N1];

// ---------------------------------------------------------------------------
// helpers
// ---------------------------------------------------------------------------
static __device__ __forceinline__ u32 s2u(const void* p){
    u32 a; asm("{ .reg .u64 t; cvta.to.shared.u64 t, %1; cvt.u32.u64 %0, t; }":"=r"(a):"l"(p)); return a;
}
static __device__ __forceinline__ u32 tf32u(float x){
    u32 r; asm("cvt.rna.tf32.f32 %0, %1;" : "=r"(r) : "f"(x)); return r;
}
static __device__ __forceinline__ float silu_f(float g){ return g / (1.f + __expf(-g)); }

static __device__ __forceinline__ void mma8(float* d, const u32* a, const u32* b){
    asm volatile("mma.sync.aligned.m16n8k8.row.col.f32.tf32.tf32.f32 "
        "{%0,%1,%2,%3}, {%4,%5,%6,%7}, {%8,%9}, {%0,%1,%2,%3};"
        : "+f"(d[0]), "+f"(d[1]), "+f"(d[2]), "+f"(d[3])
        : "r"(a[0]), "r"(a[1]), "r"(a[2]), "r"(a[3]), "r"(b[0]), "r"(b[1]));
}
static __device__ __forceinline__ void ldsm4(u32 addr, u32* r){
    asm volatile("ldmatrix.sync.aligned.m8n8.x4.shared.b16 {%0,%1,%2,%3}, [%4];"
        : "=r"(r[0]), "=r"(r[1]), "=r"(r[2]), "=r"(r[3]) : "r"(addr));
}
static __device__ __forceinline__ void cpa16(u32 dst, const void* src){
    asm volatile("cp.async.cg.shared.global [%0], [%1], 16;" :: "r"(dst), "l"(src));
}
static __device__ __forceinline__ void cpcommit(){ asm volatile("cp.async.commit_group;" ::: "memory"); }
static __device__ __forceinline__ void cpwait0(){ asm volatile("cp.async.wait_group 0;" ::: "memory"); }

// dequant one packed int32 (8 int4 ascending k) -> 8 tf32 floats
static __device__ __forceinline__ void deq8(u32 q, float s, float nzt, float* dst){
    float4 a, b;
    a.x = __uint_as_float(tf32u(fmaf((float)( q        & 15), s, nzt)));
    a.y = __uint_as_float(tf32u(fmaf((float)((q >>  4) & 15), s, nzt)));
    a.z = __uint_as_float(tf32u(fmaf((float)((q >>  8) & 15), s, nzt)));
    a.w = __uint_as_float(tf32u(fmaf((float)((q >> 12) & 15), s, nzt)));
    b.x = __uint_as_float(tf32u(fmaf((float)((q >> 16) & 15), s, nzt)));
    b.y = __uint_as_float(tf32u(fmaf((float)((q >> 20) & 15), s, nzt)));
    b.z = __uint_as_float(tf32u(fmaf((float)((q >> 24) & 15), s, nzt)));
    b.w = __uint_as_float(tf32u(fmaf((float)((q >> 28) & 15), s, nzt)));
    *(float4*)dst = a; *(float4*)(dst + 4) = b;
}

// ---------------------------------------------------------------------------
// Kernel 0: pre-round x to tf32
// ---------------------------------------------------------------------------
__global__ void roundx_k(const float* __restrict__ x){
    size_t i = (size_t)blockIdx.x * blockDim.x + threadIdx.x;
    float4 v = ((const float4*)x)[i];
    v.x = __uint_as_float(tf32u(v.x)); v.y = __uint_as_float(tf32u(v.y));
    v.z = __uint_as_float(tf32u(v.z)); v.w = __uint_as_float(tf32u(v.w));
    ((float4*)g_xr)[i] = v;
}

// ---------------------------------------------------------------------------
// Kernel A: fused gate+up GEMM (M=4096,K=4096,N=11008) + silu*mul -> g_h
// CTA 128x128, BK=64, 2-stage, 8 warps = 2(M) x 4(N), warp tile 64x32 dual.
// Fragment double-buffering + dequant interleaved into MMA loop.
// ---------------------------------------------------------------------------
#define GU_SMEM (3 * 2 * STAGE * 4)   // 208896 B

__global__ __launch_bounds__(256, 1)
void gateup_mma(const int* __restrict__ gqw, const float* __restrict__ gsc, const int* __restrict__ gqz,
                const int* __restrict__ uqw, const float* __restrict__ usc, const int* __restrict__ uqz)
{
    extern __shared__ float sm[];
    float* A0 = sm;
    float* G0 = sm + 2 * STAGE;
    float* U0 = sm + 4 * STAGE;
    const u32 sbA = s2u(A0), sbG = s2u(G0), sbU = s2u(U0);

    const int tid = threadIdx.x, wid = tid >> 5, lid = tid & 31;
    const int warpM = wid >> 2, warpN = wid & 3;
    const int n0 = blockIdx.x * 128, m0 = blockIdx.y * 128;
    const int r = lid >> 2, c = lid & 3;

    const float* xbase = g_xr + (size_t)m0 * K1;
    const int bn = tid & 127, kr = (tid >> 7) * 4;
    const int gcol = n0 + bn, zsh = (bn & 7) * 4;

    const int g8 = lid >> 3, lr = lid & 7;
    u32 almA[4];
#pragma unroll
    for (int mt = 0; mt < 4; mt++){
        int row = warpM * 64 + mt * 16 + (g8 & 1) * 8 + lr;
        almA[mt] = sbA + (u32)(row * SROW * 4) + (u32)((g8 >> 1) * 16);
    }
    const int brow = ((lid >> 4) & 1) * 8 + lr;
    const int bcol = ((lid >> 3) & 1) * 16;
    u32 almG[2], almU[2];
#pragma unroll
    for (int p = 0; p < 2; p++){
        int row = warpN * 32 + p * 16 + brow;
        almG[p] = sbG + (u32)(row * SROW * 4) + (u32)bcol;
        almU[p] = sbU + (u32)(row * SROW * 4) + (u32)bcol;
    }

    float accG[4][4][4], accU[4][4][4];
#pragma unroll
    for (int i = 0; i < 4; i++)
#pragma unroll
        for (int j = 0; j < 4; j++)
#pragma unroll
            for (int k = 0; k < 4; k++){ accG[i][j][k] = 0.f; accU[i][j][k] = 0.f; }

    const int NK = K1 / 64;   // 64
    u32 gq[4], uq[4], gz, uz; float gs, us;

#define ACOPY_GU(st, kt1) do {                                                   \
    u32 so_ = sbA + (u32)((st) * STAGE * 4);                                     \
    _Pragma("unroll")                                                            \
    for (int i_ = 0; i_ < 8; i_++){                                              \
        int id_ = tid + i_ * 256, row_ = id_ >> 4, kb_ = id_ & 15;               \
        cpa16(so_ + (u32)((row_ * SROW + kb_ * 4) * 4),                          \
              xbase + (size_t)row_ * K1 + (size_t)(kt1) * 64 + kb_ * 4);         \
    }                                                                            \
    cpcommit();                                                                  \
} while (0)

#define WLOAD_GU(kt1) do {                                                       \
    size_t wr_ = (size_t)((kt1) * 8 + kr) * N1 + gcol;                           \
    _Pragma("unroll")                                                            \
    for (int w_ = 0; w_ < 4; w_++){                                              \
        gq[w_] = __ldg((const u32*)gqw + wr_ + (size_t)w_ * N1);                 \
        uq[w_] = __ldg((const u32*)uqw + wr_ + (size_t)w_ * N1);                 \
    }                                                                            \
    int grp_ = (kt1) >> 1;                                                       \
    gs = __ldg(gsc + (size_t)grp_ * N1 + gcol);                                  \
    us = __ldg(usc + (size_t)grp_ * N1 + gcol);                                  \
    gz = __ldg((const u32*)gqz + (size_t)grp_ * (N1 / 8) + (gcol >> 3));         \
    uz = __ldg((const u32*)uqz + (size_t)grp_ * (N1 / 8) + (gcol >> 3));         \
} while (0)

    // prologue: stage 0
    ACOPY_GU(0, 0);
    WLOAD_GU(0);
    {
        float* gd = G0 + bn * SROW + kr * 8;
        float nz = -((float)(((gz >> zsh) & 15) + 1)) * gs;
#pragma unroll
        for (int w = 0; w < 4; w++) deq8(gq[w], gs, nz, gd + w * 8);
        float* ud = U0 + bn * SROW + kr * 8;
        nz = -((float)(((uz >> zsh) & 15) + 1)) * us;
#pragma unroll
        for (int w = 0; w < 4; w++) deq8(uq[w], us, nz, ud + w * 8);
    }
    cpwait0();
    __syncthreads();

    for (int kt = 0; kt < NK; ++kt){
        const int cur = kt & 1, nxt = cur ^ 1;
        const bool more = (kt + 1 < NK);
        if (more){
            ACOPY_GU(nxt, kt + 1);
            WLOAD_GU(kt + 1);
        }
        float* gdst = G0 + nxt * STAGE + bn * SROW + kr * 8;
        float* udst = U0 + nxt * STAGE + bn * SROW + kr * 8;
        const float gnz = -((float)(((gz >> zsh) & 15) + 1)) * gs;
        const float unz = -((float)(((uz >> zsh) & 15) + 1)) * us;

        const u32 so = (u32)(cur * STAGE * 4);

        // fragment pipeline buffers
        u32 afA[2][4][4], bgB[2][2][4], buB[2][2][4];
#pragma unroll
        for (int mt = 0; mt < 4; mt++) ldsm4(almA[mt] + so, afA[0][mt]);
#pragma unroll
        for (int p = 0; p < 2; p++){ ldsm4(almG[p] + so, bgB[0][p]); ldsm4(almU[p] + so, buB[0][p]); }

#pragma unroll
        for (int j = 0; j < 8; j++){
            const int cb = j & 1, nb = cb ^ 1;
            if (j < 7){
#pragma unroll
                for (int mt = 0; mt < 4; mt++) ldsm4(almA[mt] + so + (j + 1) * 32, afA[nb][mt]);
#pragma unroll
                for (int p = 0; p < 2; p++){
                    ldsm4(almG[p] + so + (j + 1) * 32, bgB[nb][p]);
                    ldsm4(almU[p] + so + (j + 1) * 32, buB[nb][p]);
                }
            }
            // interleaved dequant for next stage: one word per j
            if (more){
                if ((j & 1) == 0) deq8(gq[j >> 1], gs, gnz, gdst + (j >> 1) * 8);
                else              deq8(uq[j >> 1], us, unz, udst + (j >> 1) * 8);
            }
#pragma unroll
            for (int mt = 0; mt < 4; mt++)
#pragma unroll
                for (int nt = 0; nt < 4; nt++){
                    mma8(accG[mt][nt], afA[cb][mt], &bgB[cb][nt >> 1][(nt & 1) * 2]);
                    mma8(accU[mt][nt], afA[cb][mt], &buB[cb][nt >> 1][(nt & 1) * 2]);
                }
        }

        if (more) cpwait0();
        __syncthreads();
    }
#undef ACOPY_GU
#undef WLOAD_GU

    // epilogue: h = silu(g) * u, tf32-rounded
#pragma unroll
    for (int mt = 0; mt < 4; mt++)
#pragma unroll
        for (int nt = 0; nt < 4; nt++){
            const int row = m0 + warpM * 64 + mt * 16 + r;
            const int col = n0 + warpN * 32 + nt * 8 + c * 2;
            float* hp = g_h + (size_t)row * N1 + col;
            const float* a = accG[mt][nt]; const float* b = accU[mt][nt];
            float2 v0, v1;
            v0.x = __uint_as_float(tf32u(silu_f(a[0]) * b[0]));
            v0.y = __uint_as_float(tf32u(silu_f(a[1]) * b[1]));
            v1.x = __uint_as_float(tf32u(silu_f(a[2]) * b[2]));
            v1.y = __uint_as_float(tf32u(silu_f(a[3]) * b[3]));
            *(float2*)hp            = v0;
            *(float2*)(hp + 8 * N1) = v1;
        }
}

// ---------------------------------------------------------------------------
// Kernel B: down GEMM out = h @ Wd (M=4096, K=11008, N=4096), BK=64
// ---------------------------------------------------------------------------
#define DN_SMEM (2 * 2 * STAGE * 4)   // 139264 B

__global__ __launch_bounds__(256, 1)
void down_mma(const int* __restrict__ dqw, const float* __restrict__ dsc,
              const int* __restrict__ dqz, float* __restrict__ out)
{
    extern __shared__ float sm[];
    float* A0 = sm;
    float* B0 = sm + 2 * STAGE;
    const u32 sbA = s2u(A0), sbB = s2u(B0);

    const int tid = threadIdx.x, wid = tid >> 5, lid = tid & 31;
    const int warpM = wid >> 2, warpN = wid & 3;
    const int n0 = blockIdx.x * 128, m0 = blockIdx.y * 128;
    const int r = lid >> 2, c = lid & 3;

    const float* xbase = g_h + (size_t)m0 * N1;
    const int bn = tid & 127, kr = (tid >> 7) * 4;
    const int gcol = n0 + bn, zsh = (bn & 7) * 4;

    const int g8 = lid >> 3, lr = lid & 7;
    u32 almA[4];
#pragma unroll
    for (int mt = 0; mt < 4; mt++){
        int row = warpM * 64 + mt * 16 + (g8 & 1) * 8 + lr;
        almA[mt] = sbA + (u32)(row * SROW * 4) + (u32)((g8 >> 1) * 16);
    }
    const int brow = ((lid >> 4) & 1) * 8 + lr;
    const int bcol = ((lid >> 3) & 1) * 16;
    u32 almB[2];
#pragma unroll
    for (int p = 0; p < 2; p++){
        int row = warpN * 32 + p * 16 + brow;
        almB[p] = sbB + (u32)(row * SROW * 4) + (u32)bcol;
    }

    float acc[4][4][4];
#pragma unroll
    for (int i = 0; i < 4; i++)
#pragma unroll
        for (int j = 0; j < 4; j++)
#pragma unroll
            for (int k = 0; k < 4; k++) acc[i][j][k] = 0.f;

    const int NK = N1 / 64;   // 172
    u32 dq[4], dz; float ds;

#define ACOPY_DN(st, kt1) do {                                                   \
    u32 so_ = sbA + (u32)((st) * STAGE * 4);                                     \
    _Pragma("unroll")                                                            \
    for (int i_ = 0; i_ < 8; i_++){                                              \
        int id_ = tid + i_ * 256, row_ = id_ >> 4, kb_ = id_ & 15;               \
        cpa16(so_ + (u32)((row_ * SROW + kb_ * 4) * 4),                          \
              xbase + (size_t)row_ * N1 + (size_t)(kt1) * 64 + kb_ * 4);         \
    }                                                                            \
    cpcommit();                                                                  \
} while (0)

#define WLOAD_DN(kt1) do {                                                       \
    size_t wr_ = (size_t)((kt1) * 8 + kr) * N2 + gcol;                           \
    _Pragma("unroll")                                                            \
    for (int w_ = 0; w_ < 4; w_++)                                               \
        dq[w_] = __ldg((const u32*)dqw + wr_ + (size_t)w_ * N2);                 \
    int grp_ = (kt1) >> 1;                                                       \
    ds = __ldg(dsc + (size_t)grp_ * N2 + gcol);                                  \
    dz = __ldg((const u32*)dqz + (size_t)grp_ * (N2 / 8) + (gcol >> 3));         \
} while (0)

    ACOPY_DN(0, 0);
    WLOAD_DN(0);
    {
        float* bd = B0 + bn * SROW + kr * 8;
        float nz = -((float)(((dz >> zsh) & 15) + 1)) * ds;
#pragma unroll
        for (int w = 0; w < 4; w++) deq8(dq[w], ds, nz, bd + w * 8);
    }
    cpwait0();
    __syncthreads();

    for (int kt = 0; kt < NK; ++kt){
        const int cur = kt & 1, nxt = cur ^ 1;
        const bool more = (kt + 1 < NK);
        if (more){
            ACOPY_DN(nxt, kt + 1);
            WLOAD_DN(kt + 1);
        }
        float* bdst = B0 + nxt * STAGE + bn * SROW + kr * 8;
        const float dnz = -((float)(((dz >> zsh) & 15) + 1)) * ds;

        const u32 so = (u32)(cur * STAGE * 4);

        u32 afA[2][4][4], bfB[2][2][4];
#pragma unroll
        for (int mt = 0; mt < 4; mt++) ldsm4(almA[mt] + so, afA[0][mt]);
#pragma unroll
        for (int p = 0; p < 2; p++) ldsm4(almB[p] + so, bfB[0][p]);

#pragma unroll
        for (int j = 0; j < 8; j++){
            const int cb = j & 1, nb = cb ^ 1;
            if (j < 7){
#pragma unroll
                for (int mt = 0; mt < 4; mt++) ldsm4(almA[mt] + so + (j + 1) * 32, afA[nb][mt]);
#pragma unroll
                for (int p = 0; p < 2; p++) ldsm4(almB[p] + so + (j + 1) * 32, bfB[nb][p]);
            }
            if (more && (j & 1) == 0) deq8(dq[j >> 1], ds, dnz, bdst + (j >> 1) * 8);
#pragma unroll
            for (int mt = 0; mt < 4; mt++)
#pragma unroll
                for (int nt = 0; nt < 4; nt++)
                    mma8(acc[mt][nt], afA[cb][mt], &bfB[cb][nt >> 1][(nt & 1) * 2]);
        }

        if (more) cpwait0();
        __syncthreads();
    }
#undef ACOPY_DN
#undef WLOAD_DN

#pragma unroll
    for (int mt = 0; mt < 4; mt++)
#pragma unroll
        for (int nt = 0; nt < 4; nt++){
            const int row = m0 + warpM * 64 + mt * 16 + r;
            const int col = n0 + warpN * 32 + nt * 8 + c * 2;
            float* op = out + (size_t)row * N2 + col;
            const float* a = acc[mt][nt];
            *(float2*)op            = make_float2(a[0], a[1]);
            *(float2*)(op + 8 * N2) = make_float2(a[2], a[3]);
        }
}

// ---------------------------------------------------------------------------
// Host launcher
// ---------------------------------------------------------------------------
extern "C" void kernel_launch(void* const* d_in, const int* in_sizes, int n_in,
                              void* d_out, int out_size)
{
    (void)in_sizes; (void)n_in; (void)out_size;
    const float* x   = (const float*)d_in[0];
    const int*   gqw = (const int*)  d_in[1];
    const float* gsc = (const float*)d_in[2];
    const int*   gqz = (const int*)  d_in[3];
    const int*   uqw = (const int*)  d_in[4];
    const float* usc = (const float*)d_in[5];
    const int*   uqz = (const int*)  d_in[6];
    const int*   dqw = (const int*)  d_in[7];
    const float* dsc = (const float*)d_in[8];
    const int*   dqz = (const int*)  d_in[9];
    float* out = (float*)d_out;

    cudaFuncSetAttribute(gateup_mma, cudaFuncAttributeMaxDynamicSharedMemorySize, GU_SMEM);
    cudaFuncSetAttribute(down_mma,   cudaFuncAttributeMaxDynamicSharedMemorySize, DN_SMEM);

    roundx_k<<<(int)((size_t)M_TOT * K1 / 4 / 256), 256>>>(x);

    dim3 gridA(N1 / 128, M_TOT / 128);   // 86 x 32
    gateup_mma<<<gridA, 256, GU_SMEM>>>(gqw, gsc, gqz, uqw, usc, uqz);

    dim3 gridB(N2 / 128, M_TOT / 128);   // 32 x 32
    down_mma<<<gridB, 256, DN_SMEM>>>(dqw, dsc, dqz, out);
}

// round 14
// speedup vs baseline: 1.1434x; 1.1434x over previous
#include <cuda_runtime.h>
#include <stdint.h>

typedef unsigned int u32;

#define M_TOT 4096
#define K1    4096
#define N1    11008
#define N2    4096
#define SROW  68                    // floats per smem row: 64 + 4 pad (stride 272B, conflict-free)
#define STAGE (128 * SROW)          // floats per stage per array (34816 B)
#define NTHREADS 512

// scratch: tf32-rounded x; h = silu(g)*u stored tf32-rounded
__device__ float g_xr[(size_t)M_TOT * K1];
__device__ float g_h [(size_t)M_TOT * N1];

// ---------------------------------------------------------------------------
// helpers
// ---------------------------------------------------------------------------
static __device__ __forceinline__ u32 s2u(const void* p){
    u32 a; asm("{ .reg .u64 t; cvta.to.shared.u64 t, %1; cvt.u32.u64 %0, t; }":"=r"(a):"l"(p)); return a;
}
static __device__ __forceinline__ u32 tf32u(float x){
    u32 r; asm("cvt.rna.tf32.f32 %0, %1;" : "=r"(r) : "f"(x)); return r;
}
static __device__ __forceinline__ float silu_f(float g){ return g / (1.f + __expf(-g)); }

static __device__ __forceinline__ void mma8(float* d, const u32* a, const u32* b){
    asm volatile("mma.sync.aligned.m16n8k8.row.col.f32.tf32.tf32.f32 "
        "{%0,%1,%2,%3}, {%4,%5,%6,%7}, {%8,%9}, {%0,%1,%2,%3};"
        : "+f"(d[0]), "+f"(d[1]), "+f"(d[2]), "+f"(d[3])
        : "r"(a[0]), "r"(a[1]), "r"(a[2]), "r"(a[3]), "r"(b[0]), "r"(b[1]));
}
static __device__ __forceinline__ void ldsm4(u32 addr, u32* r){
    asm volatile("ldmatrix.sync.aligned.m8n8.x4.shared.b16 {%0,%1,%2,%3}, [%4];"
        : "=r"(r[0]), "=r"(r[1]), "=r"(r[2]), "=r"(r[3]) : "r"(addr));
}
static __device__ __forceinline__ void cpa16(u32 dst, const void* src){
    asm volatile("cp.async.cg.shared.global [%0], [%1], 16;" :: "r"(dst), "l"(src));
}
static __device__ __forceinline__ void cpcommit(){ asm volatile("cp.async.commit_group;" ::: "memory"); }
static __device__ __forceinline__ void cpwait0(){ asm volatile("cp.async.wait_group 0;" ::: "memory"); }

// dequant one packed int32 (8 int4 ascending k) -> 8 tf32 floats
static __device__ __forceinline__ void deq8(u32 q, float s, float nzt, float* dst){
    float4 a, b;
    a.x = __uint_as_float(tf32u(fmaf((float)( q        & 15), s, nzt)));
    a.y = __uint_as_float(tf32u(fmaf((float)((q >>  4) & 15), s, nzt)));
    a.z = __uint_as_float(tf32u(fmaf((float)((q >>  8) & 15), s, nzt)));
    a.w = __uint_as_float(tf32u(fmaf((float)((q >> 12) & 15), s, nzt)));
    b.x = __uint_as_float(tf32u(fmaf((float)((q >> 16) & 15), s, nzt)));
    b.y = __uint_as_float(tf32u(fmaf((float)((q >> 20) & 15), s, nzt)));
    b.z = __uint_as_float(tf32u(fmaf((float)((q >> 24) & 15), s, nzt)));
    b.w = __uint_as_float(tf32u(fmaf((float)((q >> 28) & 15), s, nzt)));
    *(float4*)dst = a; *(float4*)(dst + 4) = b;
}

// ---------------------------------------------------------------------------
// Kernel 0: pre-round x to tf32
// ---------------------------------------------------------------------------
__global__ void roundx_k(const float* __restrict__ x){
    size_t i = (size_t)blockIdx.x * blockDim.x + threadIdx.x;
    float4 v = ((const float4*)x)[i];
    v.x = __uint_as_float(tf32u(v.x)); v.y = __uint_as_float(tf32u(v.y));
    v.z = __uint_as_float(tf32u(v.z)); v.w = __uint_as_float(tf32u(v.w));
    ((float4*)g_xr)[i] = v;
}

// ---------------------------------------------------------------------------
// Kernel A: fused gate+up GEMM (M=4096,K=4096,N=11008) + silu*mul -> g_h
// CTA 128x128, BK=64, 2-stage, 16 warps = 4(M) x 4(N), warp tile 32x32 dual.
// ---------------------------------------------------------------------------
#define GU_SMEM (3 * 2 * STAGE * 4)   // 208896 B

__global__ __launch_bounds__(NTHREADS, 1)
void gateup_mma(const int* __restrict__ gqw, const float* __restrict__ gsc, const int* __restrict__ gqz,
                const int* __restrict__ uqw, const float* __restrict__ usc, const int* __restrict__ uqz)
{
    extern __shared__ float sm[];
    float* A0 = sm;
    float* G0 = sm + 2 * STAGE;
    float* U0 = sm + 4 * STAGE;
    const u32 sbA = s2u(A0), sbG = s2u(G0), sbU = s2u(U0);

    const int tid = threadIdx.x, wid = tid >> 5, lid = tid & 31;
    const int warpM = wid >> 2, warpN = wid & 3;
    const int n0 = blockIdx.x * 128, m0 = blockIdx.y * 128;
    const int r = lid >> 2, c = lid & 3;

    const float* xbase = g_xr + (size_t)m0 * K1;
    // weight loader: col = tid&127, two packed k-words starting at kr (kr in {0,2,4,6})
    const int bn = tid & 127, kr = (tid >> 7) * 2;
    const int gcol = n0 + bn, zsh = (bn & 7) * 4;

    // ldmatrix lane addresses (stage 0)
    const int g8 = lid >> 3, lr = lid & 7;
    u32 almA[2];
#pragma unroll
    for (int mt = 0; mt < 2; mt++){
        int row = warpM * 32 + mt * 16 + (g8 & 1) * 8 + lr;
        almA[mt] = sbA + (u32)(row * SROW * 4) + (u32)((g8 >> 1) * 16);
    }
    const int brow = ((lid >> 4) & 1) * 8 + lr;
    const int bcol = ((lid >> 3) & 1) * 16;
    u32 almG[2], almU[2];
#pragma unroll
    for (int p = 0; p < 2; p++){
        int row = warpN * 32 + p * 16 + brow;
        almG[p] = sbG + (u32)(row * SROW * 4) + (u32)bcol;
        almU[p] = sbU + (u32)(row * SROW * 4) + (u32)bcol;
    }

    float accG[2][4][4], accU[2][4][4];
#pragma unroll
    for (int i = 0; i < 2; i++)
#pragma unroll
        for (int j = 0; j < 4; j++)
#pragma unroll
            for (int k = 0; k < 4; k++){ accG[i][j][k] = 0.f; accU[i][j][k] = 0.f; }

    const int NK = K1 / 64;   // 64
    u32 gq[2], uq[2], gz, uz; float gs, us;

#define ACOPY_GU(st, kt1) do {                                                   \
    u32 so_ = sbA + (u32)((st) * STAGE * 4);                                     \
    _Pragma("unroll")                                                            \
    for (int i_ = 0; i_ < 4; i_++){                                              \
        int id_ = tid + i_ * NTHREADS, row_ = id_ >> 4, kb_ = id_ & 15;          \
        cpa16(so_ + (u32)((row_ * SROW + kb_ * 4) * 4),                          \
              xbase + (size_t)row_ * K1 + (size_t)(kt1) * 64 + kb_ * 4);         \
    }                                                                            \
    cpcommit();                                                                  \
} while (0)

#define WLOAD_GU(kt1) do {                                                       \
    size_t wr_ = (size_t)((kt1) * 8 + kr) * N1 + gcol;                           \
    _Pragma("unroll")                                                            \
    for (int w_ = 0; w_ < 2; w_++){                                              \
        gq[w_] = __ldg((const u32*)gqw + wr_ + (size_t)w_ * N1);                 \
        uq[w_] = __ldg((const u32*)uqw + wr_ + (size_t)w_ * N1);                 \
    }                                                                            \
    int grp_ = (kt1) >> 1;                                                       \
    gs = __ldg(gsc + (size_t)grp_ * N1 + gcol);                                  \
    us = __ldg(usc + (size_t)grp_ * N1 + gcol);                                  \
    gz = __ldg((const u32*)gqz + (size_t)grp_ * (N1 / 8) + (gcol >> 3));         \
    uz = __ldg((const u32*)uqz + (size_t)grp_ * (N1 / 8) + (gcol >> 3));         \
} while (0)

#define WSTORE_GU(st) do {                                                       \
    float* gd_ = G0 + (st) * STAGE + bn * SROW + kr * 8;                         \
    float nz_ = -((float)(((gz >> zsh) & 15) + 1)) * gs;                         \
    _Pragma("unroll")                                                            \
    for (int w_ = 0; w_ < 2; w_++) deq8(gq[w_], gs, nz_, gd_ + w_ * 8);          \
    float* ud_ = U0 + (st) * STAGE + bn * SROW + kr * 8;                         \
    nz_ = -((float)(((uz >> zsh) & 15) + 1)) * us;                               \
    _Pragma("unroll")                                                            \
    for (int w_ = 0; w_ < 2; w_++) deq8(uq[w_], us, nz_, ud_ + w_ * 8);          \
} while (0)

    // prologue: stage 0
    ACOPY_GU(0, 0);
    WLOAD_GU(0);
    WSTORE_GU(0);
    cpwait0();
    __syncthreads();

    for (int kt = 0; kt < NK; ++kt){
        const int cur = kt & 1, nxt = cur ^ 1;
        if (kt + 1 < NK){
            ACOPY_GU(nxt, kt + 1);
            WLOAD_GU(kt + 1);
        }

        const u32 so = (u32)(cur * STAGE * 4);
#pragma unroll
        for (int j = 0; j < 8; j++){
            u32 af[2][4], bg[2][4], bu[2][4];
#pragma unroll
            for (int mt = 0; mt < 2; mt++) ldsm4(almA[mt] + so + j * 32, af[mt]);
#pragma unroll
            for (int p = 0; p < 2; p++){ ldsm4(almG[p] + so + j * 32, bg[p]); ldsm4(almU[p] + so + j * 32, bu[p]); }
#pragma unroll
            for (int mt = 0; mt < 2; mt++)
#pragma unroll
                for (int nt = 0; nt < 4; nt++){
                    mma8(accG[mt][nt], af[mt], &bg[nt >> 1][(nt & 1) * 2]);
                    mma8(accU[mt][nt], af[mt], &bu[nt >> 1][(nt & 1) * 2]);
                }
        }

        if (kt + 1 < NK){
            WSTORE_GU(nxt);
            cpwait0();
        }
        __syncthreads();
    }
#undef ACOPY_GU
#undef WLOAD_GU
#undef WSTORE_GU

    // epilogue: h = silu(g) * u, tf32-rounded
#pragma unroll
    for (int mt = 0; mt < 2; mt++)
#pragma unroll
        for (int nt = 0; nt < 4; nt++){
            const int row = m0 + warpM * 32 + mt * 16 + r;
            const int col = n0 + warpN * 32 + nt * 8 + c * 2;
            float* hp = g_h + (size_t)row * N1 + col;
            const float* a = accG[mt][nt]; const float* b = accU[mt][nt];
            float2 v0, v1;
            v0.x = __uint_as_float(tf32u(silu_f(a[0]) * b[0]));
            v0.y = __uint_as_float(tf32u(silu_f(a[1]) * b[1]));
            v1.x = __uint_as_float(tf32u(silu_f(a[2]) * b[2]));
            v1.y = __uint_as_float(tf32u(silu_f(a[3]) * b[3]));
            *(float2*)hp            = v0;
            *(float2*)(hp + 8 * N1) = v1;
        }
}

// ---------------------------------------------------------------------------
// Kernel B: down GEMM out = h @ Wd (M=4096, K=11008, N=4096), BK=64
// ---------------------------------------------------------------------------
#define DN_SMEM (2 * 2 * STAGE * 4)   // 139264 B

__global__ __launch_bounds__(NTHREADS, 1)
void down_mma(const int* __restrict__ dqw, const float* __restrict__ dsc,
              const int* __restrict__ dqz, float* __restrict__ out)
{
    extern __shared__ float sm[];
    float* A0 = sm;
    float* B0 = sm + 2 * STAGE;
    const u32 sbA = s2u(A0), sbB = s2u(B0);

    const int tid = threadIdx.x, wid = tid >> 5, lid = tid & 31;
    const int warpM = wid >> 2, warpN = wid & 3;
    const int n0 = blockIdx.x * 128, m0 = blockIdx.y * 128;
    const int r = lid >> 2, c = lid & 3;

    const float* xbase = g_h + (size_t)m0 * N1;
    const int bn = tid & 127, kr = (tid >> 7) * 2;
    const int gcol = n0 + bn, zsh = (bn & 7) * 4;

    const int g8 = lid >> 3, lr = lid & 7;
    u32 almA[2];
#pragma unroll
    for (int mt = 0; mt < 2; mt++){
        int row = warpM * 32 + mt * 16 + (g8 & 1) * 8 + lr;
        almA[mt] = sbA + (u32)(row * SROW * 4) + (u32)((g8 >> 1) * 16);
    }
    const int brow = ((lid >> 4) & 1) * 8 + lr;
    const int bcol = ((lid >> 3) & 1) * 16;
    u32 almB[2];
#pragma unroll
    for (int p = 0; p < 2; p++){
        int row = warpN * 32 + p * 16 + brow;
        almB[p] = sbB + (u32)(row * SROW * 4) + (u32)bcol;
    }

    float acc[2][4][4];
#pragma unroll
    for (int i = 0; i < 2; i++)
#pragma unroll
        for (int j = 0; j < 4; j++)
#pragma unroll
            for (int k = 0; k < 4; k++) acc[i][j][k] = 0.f;

    const int NK = N1 / 64;   // 172
    u32 dq[2], dz; float ds;

#define ACOPY_DN(st, kt1) do {                                                   \
    u32 so_ = sbA + (u32)((st) * STAGE * 4);                                     \
    _Pragma("unroll")                                                            \
    for (int i_ = 0; i_ < 4; i_++){                                              \
        int id_ = tid + i_ * NTHREADS, row_ = id_ >> 4, kb_ = id_ & 15;          \
        cpa16(so_ + (u32)((row_ * SROW + kb_ * 4) * 4),                          \
              xbase + (size_t)row_ * N1 + (size_t)(kt1) * 64 + kb_ * 4);         \
    }                                                                            \
    cpcommit();                                                                  \
} while (0)

#define WLOAD_DN(kt1) do {                                                       \
    size_t wr_ = (size_t)((kt1) * 8 + kr) * N2 + gcol;                           \
    _Pragma("unroll")                                                            \
    for (int w_ = 0; w_ < 2; w_++)                                               \
        dq[w_] = __ldg((const u32*)dqw + wr_ + (size_t)w_ * N2);                 \
    int grp_ = (kt1) >> 1;                                                       \
    ds = __ldg(dsc + (size_t)grp_ * N2 + gcol);                                  \
    dz = __ldg((const u32*)dqz + (size_t)grp_ * (N2 / 8) + (gcol >> 3));         \
} while (0)

#define WSTORE_DN(st) do {                                                       \
    float* bd_ = B0 + (st) * STAGE + bn * SROW + kr * 8;                         \
    float nz_ = -((float)(((dz >> zsh) & 15) + 1)) * ds;                         \
    _Pragma("unroll")                                                            \
    for (int w_ = 0; w_ < 2; w_++) deq8(dq[w_], ds, nz_, bd_ + w_ * 8);          \
} while (0)

    ACOPY_DN(0, 0);
    WLOAD_DN(0);
    WSTORE_DN(0);
    cpwait0();
    __syncthreads();

    for (int kt = 0; kt < NK; ++kt){
        const int cur = kt & 1, nxt = cur ^ 1;
        if (kt + 1 < NK){
            ACOPY_DN(nxt, kt + 1);
            WLOAD_DN(kt + 1);
        }

        const u32 so = (u32)(cur * STAGE * 4);
#pragma unroll
        for (int j = 0; j < 8; j++){
            u32 af[2][4], bf[2][4];
#pragma unroll
            for (int mt = 0; mt < 2; mt++) ldsm4(almA[mt] + so + j * 32, af[mt]);
#pragma unroll
            for (int p = 0; p < 2; p++) ldsm4(almB[p] + so + j * 32, bf[p]);
#pragma unroll
            for (int mt = 0; mt < 2; mt++)
#pragma unroll
                for (int nt = 0; nt < 4; nt++)
                    mma8(acc[mt][nt], af[mt], &bf[nt >> 1][(nt & 1) * 2]);
        }

        if (kt + 1 < NK){
            WSTORE_DN(nxt);
            cpwait0();
        }
        __syncthreads();
    }
#undef ACOPY_DN
#undef WLOAD_DN
#undef WSTORE_DN

#pragma unroll
    for (int mt = 0; mt < 2; mt++)
#pragma unroll
        for (int nt = 0; nt < 4; nt++){
            const int row = m0 + warpM * 32 + mt * 16 + r;
            const int col = n0 + warpN * 32 + nt * 8 + c * 2;
            float* op = out + (size_t)row * N2 + col;
            const float* a = acc[mt][nt];
            *(float2*)op            = make_float2(a[0], a[1]);
            *(float2*)(op + 8 * N2) = make_float2(a[2], a[3]);
        }
}

// ---------------------------------------------------------------------------
// Host launcher
// ---------------------------------------------------------------------------
extern "C" void kernel_launch(void* const* d_in, const int* in_sizes, int n_in,
                              void* d_out, int out_size)
{
    (void)in_sizes; (void)n_in; (void)out_size;
    const float* x   = (const float*)d_in[0];
    const int*   gqw = (const int*)  d_in[1];
    const float* gsc = (const float*)d_in[2];
    const int*   gqz = (const int*)  d_in[3];
    const int*   uqw = (const int*)  d_in[4];
    const float* usc = (const float*)d_in[5];
    const int*   uqz = (const int*)  d_in[6];
    const int*   dqw = (const int*)  d_in[7];
    const float* dsc = (const float*)d_in[8];
    const int*   dqz = (const int*)  d_in[9];
    float* out = (float*)d_out;

    cudaFuncSetAttribute(gateup_mma, cudaFuncAttributeMaxDynamicSharedMemorySize, GU_SMEM);
    cudaFuncSetAttribute(down_mma,   cudaFuncAttributeMaxDynamicSharedMemorySize, DN_SMEM);

    roundx_k<<<(int)((size_t)M_TOT * K1 / 4 / 256), 256>>>(x);

    dim3 gridA(N1 / 128, M_TOT / 128);   // 86 x 32
    gateup_mma<<<gridA, NTHREADS, GU_SMEM>>>(gqw, gsc, gqz, uqw, usc, uqz);

    dim3 gridB(N2 / 128, M_TOT / 128);   // 32 x 32
    down_mma<<<gridB, NTHREADS, DN_SMEM>>>(dqw, dsc, dqz, out);
}

// round 15
// speedup vs baseline: 1.8631x; 1.6294x over previous
#include <cuda_runtime.h>
#include <cuda_fp16.h>
#include <stdint.h>

typedef unsigned int u32;

#define M_TOT 4096
#define K1    4096
#define N1    11008
#define N2    4096
#define SROWB 144                   // bytes per smem row: 64 halves (128B) + 16B pad
#define STAGEB (128 * SROWB)        // bytes per stage per array (18432 B)
#define NTHREADS 512

// scratch: fp16 x; h = silu(g)*u stored fp16
__device__ __half g_xh[(size_t)M_TOT * K1];
__device__ __half g_hh[(size_t)M_TOT * N1];

// ---------------------------------------------------------------------------
// helpers
// ---------------------------------------------------------------------------
static __device__ __forceinline__ u32 s2u(const void* p){
    u32 a; asm("{ .reg .u64 t; cvta.to.shared.u64 t, %1; cvt.u32.u64 %0, t; }":"=r"(a):"l"(p)); return a;
}
static __device__ __forceinline__ float silu_f(float g){ return g / (1.f + __expf(-g)); }

// D += A(16x16) * B(16x8), fp16 operands, fp32 accum
static __device__ __forceinline__ void mma16(float* d, const u32* a, const u32* b){
    asm volatile("mma.sync.aligned.m16n8k16.row.col.f32.f16.f16.f32 "
        "{%0,%1,%2,%3}, {%4,%5,%6,%7}, {%8,%9}, {%0,%1,%2,%3};"
        : "+f"(d[0]), "+f"(d[1]), "+f"(d[2]), "+f"(d[3])
        : "r"(a[0]), "r"(a[1]), "r"(a[2]), "r"(a[3]), "r"(b[0]), "r"(b[1]));
}
static __device__ __forceinline__ void ldsm4(u32 addr, u32* r){
    asm volatile("ldmatrix.sync.aligned.m8n8.x4.shared.b16 {%0,%1,%2,%3}, [%4];"
        : "=r"(r[0]), "=r"(r[1]), "=r"(r[2]), "=r"(r[3]) : "r"(addr));
}
static __device__ __forceinline__ void cpa16(u32 dst, const void* src){
    asm volatile("cp.async.cg.shared.global [%0], [%1], 16;" :: "r"(dst), "l"(src));
}
static __device__ __forceinline__ void cpcommit(){ asm volatile("cp.async.commit_group;" ::: "memory"); }
static __device__ __forceinline__ void cpwait0(){ asm volatile("cp.async.wait_group 0;" ::: "memory"); }

// dequant one packed int32 (8 int4 ascending k) -> 8 fp16 (16B), one STS.128
static __device__ __forceinline__ void deq8h(u32 q, float s, float nzt, void* dst){
    __half2 h[4];
    h[0] = __floats2half2_rn(fmaf((float)( q        & 15), s, nzt),
                             fmaf((float)((q >>  4) & 15), s, nzt));
    h[1] = __floats2half2_rn(fmaf((float)((q >>  8) & 15), s, nzt),
                             fmaf((float)((q >> 12) & 15), s, nzt));
    h[2] = __floats2half2_rn(fmaf((float)((q >> 16) & 15), s, nzt),
                             fmaf((float)((q >> 20) & 15), s, nzt));
    h[3] = __floats2half2_rn(fmaf((float)((q >> 24) & 15), s, nzt),
                             fmaf((float)((q >> 28) & 15), s, nzt));
    *(uint4*)dst = *(const uint4*)h;
}

// ---------------------------------------------------------------------------
// Kernel 0: convert x to fp16 (8 floats -> 8 halves per thread)
// ---------------------------------------------------------------------------
__global__ void cvtx_k(const float* __restrict__ x){
    size_t i = (size_t)blockIdx.x * blockDim.x + threadIdx.x;
    float4 v0 = ((const float4*)x)[i * 2];
    float4 v1 = ((const float4*)x)[i * 2 + 1];
    __half2 h[4];
    h[0] = __floats2half2_rn(v0.x, v0.y);
    h[1] = __floats2half2_rn(v0.z, v0.w);
    h[2] = __floats2half2_rn(v1.x, v1.y);
    h[3] = __floats2half2_rn(v1.z, v1.w);
    ((uint4*)g_xh)[i] = *(const uint4*)h;
}

// ---------------------------------------------------------------------------
// Kernel A: fused gate+up GEMM (M=4096,K=4096,N=11008) + silu*mul -> g_hh
// CTA 128x128, BK=64, 2-stage, 16 warps = 4(M) x 4(N), warp tile 32x32 dual.
// fp16 operands, fp32 accumulate, m16n8k16.
// ---------------------------------------------------------------------------
#define GU_SMEM (3 * 2 * STAGEB)   // 110592 B

__global__ __launch_bounds__(NTHREADS, 1)
void gateup_mma(const int* __restrict__ gqw, const float* __restrict__ gsc, const int* __restrict__ gqz,
                const int* __restrict__ uqw, const float* __restrict__ usc, const int* __restrict__ uqz)
{
    extern __shared__ char smc[];
    char* A0 = smc;
    char* G0 = smc + 2 * STAGEB;
    char* U0 = smc + 4 * STAGEB;
    const u32 sbA = s2u(A0), sbG = s2u(G0), sbU = s2u(U0);

    const int tid = threadIdx.x, wid = tid >> 5, lid = tid & 31;
    const int warpM = wid >> 2, warpN = wid & 3;
    const int n0 = blockIdx.x * 128, m0 = blockIdx.y * 128;
    const int r = lid >> 2, c = lid & 3;

    const __half* xbase = g_xh + (size_t)m0 * K1;
    // weight loader: col = tid&127, two packed k-words starting at kr (kr in {0,2,4,6})
    const int bn = tid & 127, kr = (tid >> 7) * 2;
    const int gcol = n0 + bn, zsh = (bn & 7) * 4;

    // A ldmatrix lane addresses: tiles (m0-7,k0-7),(m8-15,k0-7),(m0-7,k8-15),(m8-15,k8-15)
    const int g8 = lid >> 3, lr = lid & 7;
    u32 almA[2];
#pragma unroll
    for (int mt = 0; mt < 2; mt++){
        int row = warpM * 32 + mt * 16 + (g8 & 1) * 8 + lr;
        almA[mt] = sbA + (u32)(row * SROWB) + (u32)((g8 >> 1) * 16);
    }
    // B ldmatrix lane addresses: tiles (n0-7,k0-7),(n0-7,k8-15),(n8-15,k0-7),(n8-15,k8-15)
    const int bnrow = (lid & 7) + ((lid >> 4) & 1) * 8;
    const int bkseg = (lid >> 3) & 1;
    u32 almG[2], almU[2];
#pragma unroll
    for (int p = 0; p < 2; p++){
        int row = warpN * 32 + p * 16 + bnrow;
        almG[p] = sbG + (u32)(row * SROWB) + (u32)(bkseg * 16);
        almU[p] = sbU + (u32)(row * SROWB) + (u32)(bkseg * 16);
    }

    float accG[2][4][4], accU[2][4][4];
#pragma unroll
    for (int i = 0; i < 2; i++)
#pragma unroll
        for (int j = 0; j < 4; j++)
#pragma unroll
            for (int k = 0; k < 4; k++){ accG[i][j][k] = 0.f; accU[i][j][k] = 0.f; }

    const int NK = K1 / 64;   // 64
    u32 gq[2], uq[2], gz, uz; float gs, us;

#define ACOPY_GU(st, kt1) do {                                                   \
    u32 so_ = sbA + (u32)((st) * STAGEB);                                        \
    _Pragma("unroll")                                                            \
    for (int i_ = 0; i_ < 2; i_++){                                              \
        int id_ = tid + i_ * NTHREADS, row_ = id_ >> 3, seg_ = id_ & 7;          \
        cpa16(so_ + (u32)(row_ * SROWB + seg_ * 16),                             \
              xbase + (size_t)row_ * K1 + (size_t)(kt1) * 64 + seg_ * 8);        \
    }                                                                            \
    cpcommit();                                                                  \
} while (0)

#define WLOAD_GU(kt1) do {                                                       \
    size_t wr_ = (size_t)((kt1) * 8 + kr) * N1 + gcol;                           \
    _Pragma("unroll")                                                            \
    for (int w_ = 0; w_ < 2; w_++){                                              \
        gq[w_] = __ldg((const u32*)gqw + wr_ + (size_t)w_ * N1);                 \
        uq[w_] = __ldg((const u32*)uqw + wr_ + (size_t)w_ * N1);                 \
    }                                                                            \
    int grp_ = (kt1) >> 1;                                                       \
    gs = __ldg(gsc + (size_t)grp_ * N1 + gcol);                                  \
    us = __ldg(usc + (size_t)grp_ * N1 + gcol);                                  \
    gz = __ldg((const u32*)gqz + (size_t)grp_ * (N1 / 8) + (gcol >> 3));         \
    uz = __ldg((const u32*)uqz + (size_t)grp_ * (N1 / 8) + (gcol >> 3));         \
} while (0)

#define WSTORE_GU(st) do {                                                       \
    char* gd_ = G0 + (st) * STAGEB + bn * SROWB + kr * 16;                       \
    float nz_ = -((float)(((gz >> zsh) & 15) + 1)) * gs;                         \
    _Pragma("unroll")                                                            \
    for (int w_ = 0; w_ < 2; w_++) deq8h(gq[w_], gs, nz_, gd_ + w_ * 16);        \
    char* ud_ = U0 + (st) * STAGEB + bn * SROWB + kr * 16;                       \
    nz_ = -((float)(((uz >> zsh) & 15) + 1)) * us;                               \
    _Pragma("unroll")                                                            \
    for (int w_ = 0; w_ < 2; w_++) deq8h(uq[w_], us, nz_, ud_ + w_ * 16);        \
} while (0)

    // prologue: stage 0
    ACOPY_GU(0, 0);
    WLOAD_GU(0);
    WSTORE_GU(0);
    cpwait0();
    __syncthreads();

    for (int kt = 0; kt < NK; ++kt){
        const int cur = kt & 1, nxt = cur ^ 1;
        if (kt + 1 < NK){
            ACOPY_GU(nxt, kt + 1);
            WLOAD_GU(kt + 1);
        }

        const u32 so = (u32)(cur * STAGEB);
#pragma unroll
        for (int j = 0; j < 4; j++){          // j = k16 index within BK=64
            u32 af[2][4], bg[2][4], bu[2][4];
#pragma unroll
            for (int mt = 0; mt < 2; mt++) ldsm4(almA[mt] + so + j * 32, af[mt]);
#pragma unroll
            for (int p = 0; p < 2; p++){ ldsm4(almG[p] + so + j * 32, bg[p]); ldsm4(almU[p] + so + j * 32, bu[p]); }
#pragma unroll
            for (int mt = 0; mt < 2; mt++)
#pragma unroll
                for (int nt = 0; nt < 4; nt++){
                    mma16(accG[mt][nt], af[mt], &bg[nt >> 1][(nt & 1) * 2]);
                    mma16(accU[mt][nt], af[mt], &bu[nt >> 1][(nt & 1) * 2]);
                }
        }

        if (kt + 1 < NK){
            WSTORE_GU(nxt);
            cpwait0();
        }
        __syncthreads();
    }
#undef ACOPY_GU
#undef WLOAD_GU
#undef WSTORE_GU

    // epilogue: h = silu(g) * u -> fp16
#pragma unroll
    for (int mt = 0; mt < 2; mt++)
#pragma unroll
        for (int nt = 0; nt < 4; nt++){
            const int row = m0 + warpM * 32 + mt * 16 + r;
            const int col = n0 + warpN * 32 + nt * 8 + c * 2;
            __half* hp = g_hh + (size_t)row * N1 + col;
            const float* a = accG[mt][nt]; const float* b = accU[mt][nt];
            *(__half2*)hp            = __floats2half2_rn(silu_f(a[0]) * b[0], silu_f(a[1]) * b[1]);
            *(__half2*)(hp + 8 * N1) = __floats2half2_rn(silu_f(a[2]) * b[2], silu_f(a[3]) * b[3]);
        }
}

// ---------------------------------------------------------------------------
// Kernel B: down GEMM out = h @ Wd (M=4096, K=11008, N=4096), BK=64, fp16
// ---------------------------------------------------------------------------
#define DN_SMEM (2 * 2 * STAGEB)   // 73728 B

__global__ __launch_bounds__(NTHREADS, 1)
void down_mma(const int* __restrict__ dqw, const float* __restrict__ dsc,
              const int* __restrict__ dqz, float* __restrict__ out)
{
    extern __shared__ char smc[];
    char* A0 = smc;
    char* B0 = smc + 2 * STAGEB;
    const u32 sbA = s2u(A0), sbB = s2u(B0);

    const int tid = threadIdx.x, wid = tid >> 5, lid = tid & 31;
    const int warpM = wid >> 2, warpN = wid & 3;
    const int n0 = blockIdx.x * 128, m0 = blockIdx.y * 128;
    const int r = lid >> 2, c = lid & 3;

    const __half* xbase = g_hh + (size_t)m0 * N1;
    const int bn = tid & 127, kr = (tid >> 7) * 2;
    const int gcol = n0 + bn, zsh = (bn & 7) * 4;

    const int g8 = lid >> 3, lr = lid & 7;
    u32 almA[2];
#pragma unroll
    for (int mt = 0; mt < 2; mt++){
        int row = warpM * 32 + mt * 16 + (g8 & 1) * 8 + lr;
        almA[mt] = sbA + (u32)(row * SROWB) + (u32)((g8 >> 1) * 16);
    }
    const int bnrow = (lid & 7) + ((lid >> 4) & 1) * 8;
    const int bkseg = (lid >> 3) & 1;
    u32 almB[2];
#pragma unroll
    for (int p = 0; p < 2; p++){
        int row = warpN * 32 + p * 16 + bnrow;
        almB[p] = sbB + (u32)(row * SROWB) + (u32)(bkseg * 16);
    }

    float acc[2][4][4];
#pragma unroll
    for (int i = 0; i < 2; i++)
#pragma unroll
        for (int j = 0; j < 4; j++)
#pragma unroll
            for (int k = 0; k < 4; k++) acc[i][j][k] = 0.f;

    const int NK = N1 / 64;   // 172
    u32 dq[2], dz; float ds;

#define ACOPY_DN(st, kt1) do {                                                   \
    u32 so_ = sbA + (u32)((st) * STAGEB);                                        \
    _Pragma("unroll")                                                            \
    for (int i_ = 0; i_ < 2; i_++){                                              \
        int id_ = tid + i_ * NTHREADS, row_ = id_ >> 3, seg_ = id_ & 7;          \
        cpa16(so_ + (u32)(row_ * SROWB + seg_ * 16),                             \
              xbase + (size_t)row_ * N1 + (size_t)(kt1) * 64 + seg_ * 8);        \
    }                                                                            \
    cpcommit();                                                                  \
} while (0)

#define WLOAD_DN(kt1) do {                                                       \
    size_t wr_ = (size_t)((kt1) * 8 + kr) * N2 + gcol;                           \
    _Pragma("unroll")                                                            \
    for (int w_ = 0; w_ < 2; w_++)                                               \
        dq[w_] = __ldg((const u32*)dqw + wr_ + (size_t)w_ * N2);                 \
    int grp_ = (kt1) >> 1;                                                       \
    ds = __ldg(dsc + (size_t)grp_ * N2 + gcol);                                  \
    dz = __ldg((const u32*)dqz + (size_t)grp_ * (N2 / 8) + (gcol >> 3));         \
} while (0)

#define WSTORE_DN(st) do {                                                       \
    char* bd_ = B0 + (st) * STAGEB + bn * SROWB + kr * 16;                       \
    float nz_ = -((float)(((dz >> zsh) & 15) + 1)) * ds;                         \
    _Pragma("unroll")                                                            \
    for (int w_ = 0; w_ < 2; w_++) deq8h(dq[w_], ds, nz_, bd_ + w_ * 16);        \
} while (0)

    ACOPY_DN(0, 0);
    WLOAD_DN(0);
    WSTORE_DN(0);
    cpwait0();
    __syncthreads();

    for (int kt = 0; kt < NK; ++kt){
        const int cur = kt & 1, nxt = cur ^ 1;
        if (kt + 1 < NK){
            ACOPY_DN(nxt, kt + 1);
            WLOAD_DN(kt + 1);
        }

        const u32 so = (u32)(cur * STAGEB);
#pragma unroll
        for (int j = 0; j < 4; j++){
            u32 af[2][4], bf[2][4];
#pragma unroll
            for (int mt = 0; mt < 2; mt++) ldsm4(almA[mt] + so + j * 32, af[mt]);
#pragma unroll
            for (int p = 0; p < 2; p++) ldsm4(almB[p] + so + j * 32, bf[p]);
#pragma unroll
            for (int mt = 0; mt < 2; mt++)
#pragma unroll
                for (int nt = 0; nt < 4; nt++)
                    mma16(acc[mt][nt], af[mt], &bf[nt >> 1][(nt & 1) * 2]);
        }

        if (kt + 1 < NK){
            WSTORE_DN(nxt);
            cpwait0();
        }
        __syncthreads();
    }
#undef ACOPY_DN
#undef WLOAD_DN
#undef WSTORE_DN

#pragma unroll
    for (int mt = 0; mt < 2; mt++)
#pragma unroll
        for (int nt = 0; nt < 4; nt++){
            const int row = m0 + warpM * 32 + mt * 16 + r;
            const int col = n0 + warpN * 32 + nt * 8 + c * 2;
            float* op = out + (size_t)row * N2 + col;
            const float* a = acc[mt][nt];
            *(float2*)op            = make_float2(a[0], a[1]);
            *(float2*)(op + 8 * N2) = make_float2(a[2], a[3]);
        }
}

// ---------------------------------------------------------------------------
// Host launcher
// ---------------------------------------------------------------------------
extern "C" void kernel_launch(void* const* d_in, const int* in_sizes, int n_in,
                              void* d_out, int out_size)
{
    (void)in_sizes; (void)n_in; (void)out_size;
    const float* x   = (const float*)d_in[0];
    const int*   gqw = (const int*)  d_in[1];
    const float* gsc = (const float*)d_in[2];
    const int*   gqz = (const int*)  d_in[3];
    const int*   uqw = (const int*)  d_in[4];
    const float* usc = (const float*)d_in[5];
    const int*   uqz = (const int*)  d_in[6];
    const int*   dqw = (const int*)  d_in[7];
    const float* dsc = (const float*)d_in[8];
    const int*   dqz = (const int*)  d_in[9];
    float* out = (float*)d_out;

    cudaFuncSetAttribute(gateup_mma, cudaFuncAttributeMaxDynamicSharedMemorySize, GU_SMEM);
    cudaFuncSetAttribute(down_mma,   cudaFuncAttributeMaxDynamicSharedMemorySize, DN_SMEM);

    cvtx_k<<<(int)((size_t)M_TOT * K1 / 8 / 256), 256>>>(x);

    dim3 gridA(N1 / 128, M_TOT / 128);   // 86 x 32
    gateup_mma<<<gridA, NTHREADS, GU_SMEM>>>(gqw, gsc, gqz, uqw, usc, uqz);

    dim3 gridB(N2 / 128, M_TOT / 128);   // 32 x 32
    down_mma<<<gridB, NTHREADS, DN_SMEM>>>(dqw, dsc, dqz, out);
}

// round 16
// speedup vs baseline: 1.9318x; 1.0369x over previous
#include <cuda_runtime.h>
#include <cuda_fp16.h>
#include <stdint.h>

typedef unsigned int u32;

#define M_TOT 4096
#define K1    4096
#define N1    11008
#define N2    4096
#define SROWB 144                   // bytes per smem row: 64 halves (128B) + 16B pad
#define STAGEB (128 * SROWB)        // bytes per stage per array (18432 B)
#define NTHREADS 256

// scratch: fp16 x; h = silu(g)*u stored fp16
__device__ __half g_xh[(size_t)M_TOT * K1];
__device__ __half g_hh[(size_t)M_TOT * N1];

// ---------------------------------------------------------------------------
// helpers
// ---------------------------------------------------------------------------
static __device__ __forceinline__ u32 s2u(const void* p){
    u32 a; asm("{ .reg .u64 t; cvta.to.shared.u64 t, %1; cvt.u32.u64 %0, t; }":"=r"(a):"l"(p)); return a;
}
static __device__ __forceinline__ float silu_f(float g){ return g / (1.f + __expf(-g)); }

// D += A(16x16) * B(16x8), fp16 operands, fp32 accum
static __device__ __forceinline__ void mma16(float* d, const u32* a, const u32* b){
    asm volatile("mma.sync.aligned.m16n8k16.row.col.f32.f16.f16.f32 "
        "{%0,%1,%2,%3}, {%4,%5,%6,%7}, {%8,%9}, {%0,%1,%2,%3};"
        : "+f"(d[0]), "+f"(d[1]), "+f"(d[2]), "+f"(d[3])
        : "r"(a[0]), "r"(a[1]), "r"(a[2]), "r"(a[3]), "r"(b[0]), "r"(b[1]));
}
static __device__ __forceinline__ void ldsm4(u32 addr, u32* r){
    asm volatile("ldmatrix.sync.aligned.m8n8.x4.shared.b16 {%0,%1,%2,%3}, [%4];"
        : "=r"(r[0]), "=r"(r[1]), "=r"(r[2]), "=r"(r[3]) : "r"(addr));
}
static __device__ __forceinline__ void cpa16(u32 dst, const void* src){
    asm volatile("cp.async.cg.shared.global [%0], [%1], 16;" :: "r"(dst), "l"(src));
}
static __device__ __forceinline__ void cpcommit(){ asm volatile("cp.async.commit_group;" ::: "memory"); }
static __device__ __forceinline__ void cpwait0(){ asm volatile("cp.async.wait_group 0;" ::: "memory"); }

// dequant one packed int32 (8 int4 ascending k) -> 8 fp16 (16B), one STS.128
static __device__ __forceinline__ void deq8h(u32 q, float s, float nzt, void* dst){
    __half2 h[4];
    h[0] = __floats2half2_rn(fmaf((float)( q        & 15), s, nzt),
                             fmaf((float)((q >>  4) & 15), s, nzt));
    h[1] = __floats2half2_rn(fmaf((float)((q >>  8) & 15), s, nzt),
                             fmaf((float)((q >> 12) & 15), s, nzt));
    h[2] = __floats2half2_rn(fmaf((float)((q >> 16) & 15), s, nzt),
                             fmaf((float)((q >> 20) & 15), s, nzt));
    h[3] = __floats2half2_rn(fmaf((float)((q >> 24) & 15), s, nzt),
                             fmaf((float)((q >> 28) & 15), s, nzt));
    *(uint4*)dst = *(const uint4*)h;
}

// ---------------------------------------------------------------------------
// Kernel 0: convert x to fp16 (8 floats -> 8 halves per thread)
// ---------------------------------------------------------------------------
__global__ void cvtx_k(const float* __restrict__ x){
    size_t i = (size_t)blockIdx.x * blockDim.x + threadIdx.x;
    float4 v0 = ((const float4*)x)[i * 2];
    float4 v1 = ((const float4*)x)[i * 2 + 1];
    __half2 h[4];
    h[0] = __floats2half2_rn(v0.x, v0.y);
    h[1] = __floats2half2_rn(v0.z, v0.w);
    h[2] = __floats2half2_rn(v1.x, v1.y);
    h[3] = __floats2half2_rn(v1.z, v1.w);
    ((uint4*)g_xh)[i] = *(const uint4*)h;
}

// ---------------------------------------------------------------------------
// Kernel A: fused gate+up GEMM (M=4096,K=4096,N=11008) + silu*mul -> g_hh
// CTA 128x128, BK=64, 2-stage, 8 warps = 2(M) x 4(N), warp tile 64x32 dual.
// fp16 operands, fp32 accumulate, m16n8k16.
// ---------------------------------------------------------------------------
#define GU_SMEM (3 * 2 * STAGEB)   // 110592 B

__global__ __launch_bounds__(NTHREADS, 1)
void gateup_mma(const int* __restrict__ gqw, const float* __restrict__ gsc, const int* __restrict__ gqz,
                const int* __restrict__ uqw, const float* __restrict__ usc, const int* __restrict__ uqz)
{
    extern __shared__ char smc[];
    char* A0 = smc;
    char* G0 = smc + 2 * STAGEB;
    char* U0 = smc + 4 * STAGEB;
    const u32 sbA = s2u(A0), sbG = s2u(G0), sbU = s2u(U0);

    const int tid = threadIdx.x, wid = tid >> 5, lid = tid & 31;
    const int warpM = wid >> 2, warpN = wid & 3;
    const int n0 = blockIdx.x * 128, m0 = blockIdx.y * 128;
    const int r = lid >> 2, c = lid & 3;

    const __half* xbase = g_xh + (size_t)m0 * K1;
    // weight loader: col = tid&127, four packed k-words starting at kr (kr in {0,4})
    const int bn = tid & 127, kr = (tid >> 7) * 4;
    const int gcol = n0 + bn, zsh = (bn & 7) * 4;

    // A ldmatrix lane addresses: 4 m16 tiles
    const int g8 = lid >> 3, lr = lid & 7;
    u32 almA[4];
#pragma unroll
    for (int mt = 0; mt < 4; mt++){
        int row = warpM * 64 + mt * 16 + (g8 & 1) * 8 + lr;
        almA[mt] = sbA + (u32)(row * SROWB) + (u32)((g8 >> 1) * 16);
    }
    // B ldmatrix lane addresses
    const int bnrow = (lid & 7) + ((lid >> 4) & 1) * 8;
    const int bkseg = (lid >> 3) & 1;
    u32 almG[2], almU[2];
#pragma unroll
    for (int p = 0; p < 2; p++){
        int row = warpN * 32 + p * 16 + bnrow;
        almG[p] = sbG + (u32)(row * SROWB) + (u32)(bkseg * 16);
        almU[p] = sbU + (u32)(row * SROWB) + (u32)(bkseg * 16);
    }

    float accG[4][4][4], accU[4][4][4];
#pragma unroll
    for (int i = 0; i < 4; i++)
#pragma unroll
        for (int j = 0; j < 4; j++)
#pragma unroll
            for (int k = 0; k < 4; k++){ accG[i][j][k] = 0.f; accU[i][j][k] = 0.f; }

    const int NK = K1 / 64;   // 64
    u32 gq[4], uq[4], gz, uz; float gs, us;

#define ACOPY_GU(st, kt1) do {                                                   \
    u32 so_ = sbA + (u32)((st) * STAGEB);                                        \
    _Pragma("unroll")                                                            \
    for (int i_ = 0; i_ < 4; i_++){                                              \
        int id_ = tid + i_ * NTHREADS, row_ = id_ >> 3, seg_ = id_ & 7;          \
        cpa16(so_ + (u32)(row_ * SROWB + seg_ * 16),                             \
              xbase + (size_t)row_ * K1 + (size_t)(kt1) * 64 + seg_ * 8);        \
    }                                                                            \
    cpcommit();                                                                  \
} while (0)

#define WLOAD_GU(kt1) do {                                                       \
    size_t wr_ = (size_t)((kt1) * 8 + kr) * N1 + gcol;                           \
    _Pragma("unroll")                                                            \
    for (int w_ = 0; w_ < 4; w_++){                                              \
        gq[w_] = __ldg((const u32*)gqw + wr_ + (size_t)w_ * N1);                 \
        uq[w_] = __ldg((const u32*)uqw + wr_ + (size_t)w_ * N1);                 \
    }                                                                            \
    int grp_ = (kt1) >> 1;                                                       \
    gs = __ldg(gsc + (size_t)grp_ * N1 + gcol);                                  \
    us = __ldg(usc + (size_t)grp_ * N1 + gcol);                                  \
    gz = __ldg((const u32*)gqz + (size_t)grp_ * (N1 / 8) + (gcol >> 3));         \
    uz = __ldg((const u32*)uqz + (size_t)grp_ * (N1 / 8) + (gcol >> 3));         \
} while (0)

#define WSTORE_GU(st) do {                                                       \
    char* gd_ = G0 + (st) * STAGEB + bn * SROWB + kr * 16;                       \
    float nz_ = -((float)(((gz >> zsh) & 15) + 1)) * gs;                         \
    _Pragma("unroll")                                                            \
    for (int w_ = 0; w_ < 4; w_++) deq8h(gq[w_], gs, nz_, gd_ + w_ * 16);        \
    char* ud_ = U0 + (st) * STAGEB + bn * SROWB + kr * 16;                       \
    nz_ = -((float)(((uz >> zsh) & 15) + 1)) * us;                               \
    _Pragma("unroll")                                                            \
    for (int w_ = 0; w_ < 4; w_++) deq8h(uq[w_], us, nz_, ud_ + w_ * 16);        \
} while (0)

    // prologue: stage 0
    ACOPY_GU(0, 0);
    WLOAD_GU(0);
    WSTORE_GU(0);
    cpwait0();
    __syncthreads();

    for (int kt = 0; kt < NK; ++kt){
        const int cur = kt & 1, nxt = cur ^ 1;
        if (kt + 1 < NK){
            ACOPY_GU(nxt, kt + 1);
            WLOAD_GU(kt + 1);
        }

        const u32 so = (u32)(cur * STAGEB);
#pragma unroll
        for (int j = 0; j < 4; j++){          // j = k16 index within BK=64
            u32 af[4][4], bg[2][4], bu[2][4];
#pragma unroll
            for (int mt = 0; mt < 4; mt++) ldsm4(almA[mt] + so + j * 32, af[mt]);
#pragma unroll
            for (int p = 0; p < 2; p++){ ldsm4(almG[p] + so + j * 32, bg[p]); ldsm4(almU[p] + so + j * 32, bu[p]); }
#pragma unroll
            for (int mt = 0; mt < 4; mt++)
#pragma unroll
                for (int nt = 0; nt < 4; nt++){
                    mma16(accG[mt][nt], af[mt], &bg[nt >> 1][(nt & 1) * 2]);
                    mma16(accU[mt][nt], af[mt], &bu[nt >> 1][(nt & 1) * 2]);
                }
        }

        if (kt + 1 < NK){
            WSTORE_GU(nxt);
            cpwait0();
        }
        __syncthreads();
    }
#undef ACOPY_GU
#undef WLOAD_GU
#undef WSTORE_GU

    // epilogue: h = silu(g) * u -> fp16
#pragma unroll
    for (int mt = 0; mt < 4; mt++)
#pragma unroll
        for (int nt = 0; nt < 4; nt++){
            const int row = m0 + warpM * 64 + mt * 16 + r;
            const int col = n0 + warpN * 32 + nt * 8 + c * 2;
            __half* hp = g_hh + (size_t)row * N1 + col;
            const float* a = accG[mt][nt]; const float* b = accU[mt][nt];
            *(__half2*)hp            = __floats2half2_rn(silu_f(a[0]) * b[0], silu_f(a[1]) * b[1]);
            *(__half2*)(hp + 8 * N1) = __floats2half2_rn(silu_f(a[2]) * b[2], silu_f(a[3]) * b[3]);
        }
}

// ---------------------------------------------------------------------------
// Kernel B: down GEMM out = h @ Wd (M=4096, K=11008, N=4096), BK=64, fp16
// ---------------------------------------------------------------------------
#define DN_SMEM (2 * 2 * STAGEB)   // 73728 B

__global__ __launch_bounds__(NTHREADS, 1)
void down_mma(const int* __restrict__ dqw, const float* __restrict__ dsc,
              const int* __restrict__ dqz, float* __restrict__ out)
{
    extern __shared__ char smc[];
    char* A0 = smc;
    char* B0 = smc + 2 * STAGEB;
    const u32 sbA = s2u(A0), sbB = s2u(B0);

    const int tid = threadIdx.x, wid = tid >> 5, lid = tid & 31;
    const int warpM = wid >> 2, warpN = wid & 3;
    const int n0 = blockIdx.x * 128, m0 = blockIdx.y * 128;
    const int r = lid >> 2, c = lid & 3;

    const __half* xbase = g_hh + (size_t)m0 * N1;
    const int bn = tid & 127, kr = (tid >> 7) * 4;
    const int gcol = n0 + bn, zsh = (bn & 7) * 4;

    const int g8 = lid >> 3, lr = lid & 7;
    u32 almA[4];
#pragma unroll
    for (int mt = 0; mt < 4; mt++){
        int row = warpM * 64 + mt * 16 + (g8 & 1) * 8 + lr;
        almA[mt] = sbA + (u32)(row * SROWB) + (u32)((g8 >> 1) * 16);
    }
    const int bnrow = (lid & 7) + ((lid >> 4) & 1) * 8;
    const int bkseg = (lid >> 3) & 1;
    u32 almB[2];
#pragma unroll
    for (int p = 0; p < 2; p++){
        int row = warpN * 32 + p * 16 + bnrow;
        almB[p] = sbB + (u32)(row * SROWB) + (u32)(bkseg * 16);
    }

    float acc[4][4][4];
#pragma unroll
    for (int i = 0; i < 4; i++)
#pragma unroll
        for (int j = 0; j < 4; j++)
#pragma unroll
            for (int k = 0; k < 4; k++) acc[i][j][k] = 0.f;

    const int NK = N1 / 64;   // 172
    u32 dq[4], dz; float ds;

#define ACOPY_DN(st, kt1) do {                                                   \
    u32 so_ = sbA + (u32)((st) * STAGEB);                                        \
    _Pragma("unroll")                                                            \
    for (int i_ = 0; i_ < 4; i_++){                                              \
        int id_ = tid + i_ * NTHREADS, row_ = id_ >> 3, seg_ = id_ & 7;          \
        cpa16(so_ + (u32)(row_ * SROWB + seg_ * 16),                             \
              xbase + (size_t)row_ * N1 + (size_t)(kt1) * 64 + seg_ * 8);        \
    }                                                                            \
    cpcommit();                                                                  \
} while (0)

#define WLOAD_DN(kt1) do {                                                       \
    size_t wr_ = (size_t)((kt1) * 8 + kr) * N2 + gcol;                           \
    _Pragma("unroll")                                                            \
    for (int w_ = 0; w_ < 4; w_++)                                               \
        dq[w_] = __ldg((const u32*)dqw + wr_ + (size_t)w_ * N2);                 \
    int grp_ = (kt1) >> 1;                                                       \
    ds = __ldg(dsc + (size_t)grp_ * N2 + gcol);                                  \
    dz = __ldg((const u32*)dqz + (size_t)grp_ * (N2 / 8) + (gcol >> 3));         \
} while (0)

#define WSTORE_DN(st) do {                                                       \
    char* bd_ = B0 + (st) * STAGEB + bn * SROWB + kr * 16;                       \
    float nz_ = -((float)(((dz >> zsh) & 15) + 1)) * ds;                         \
    _Pragma("unroll")                                                            \
    for (int w_ = 0; w_ < 4; w_++) deq8h(dq[w_], ds, nz_, bd_ + w_ * 16);        \
} while (0)

    ACOPY_DN(0, 0);
    WLOAD_DN(0);
    WSTORE_DN(0);
    cpwait0();
    __syncthreads();

    for (int kt = 0; kt < NK; ++kt){
        const int cur = kt & 1, nxt = cur ^ 1;
        if (kt + 1 < NK){
            ACOPY_DN(nxt, kt + 1);
            WLOAD_DN(kt + 1);
        }

        const u32 so = (u32)(cur * STAGEB);
#pragma unroll
        for (int j = 0; j < 4; j++){
            u32 af[4][4], bf[2][4];
#pragma unroll
            for (int mt = 0; mt < 4; mt++) ldsm4(almA[mt] + so + j * 32, af[mt]);
#pragma unroll
            for (int p = 0; p < 2; p++) ldsm4(almB[p] + so + j * 32, bf[p]);
#pragma unroll
            for (int mt = 0; mt < 4; mt++)
#pragma unroll
                for (int nt = 0; nt < 4; nt++)
                    mma16(acc[mt][nt], af[mt], &bf[nt >> 1][(nt & 1) * 2]);
        }

        if (kt + 1 < NK){
            WSTORE_DN(nxt);
            cpwait0();
        }
        __syncthreads();
    }
#undef ACOPY_DN
#undef WLOAD_DN
#undef WSTORE_DN

#pragma unroll
    for (int mt = 0; mt < 4; mt++)
#pragma unroll
        for (int nt = 0; nt < 4; nt++){
            const int row = m0 + warpM * 64 + mt * 16 + r;
            const int col = n0 + warpN * 32 + nt * 8 + c * 2;
            float* op = out + (size_t)row * N2 + col;
            const float* a = acc[mt][nt];
            *(float2*)op            = make_float2(a[0], a[1]);
            *(float2*)(op + 8 * N2) = make_float2(a[2], a[3]);
        }
}

// ---------------------------------------------------------------------------
// Host launcher
// ---------------------------------------------------------------------------
extern "C" void kernel_launch(void* const* d_in, const int* in_sizes, int n_in,
                              void* d_out, int out_size)
{
    (void)in_sizes; (void)n_in; (void)out_size;
    const float* x   = (const float*)d_in[0];
    const int*   gqw = (const int*)  d_in[1];
    const float* gsc = (const float*)d_in[2];
    const int*   gqz = (const int*)  d_in[3];
    const int*   uqw = (const int*)  d_in[4];
    const float* usc = (const float*)d_in[5];
    const int*   uqz = (const int*)  d_in[6];
    const int*   dqw = (const int*)  d_in[7];
    const float* dsc = (const float*)d_in[8];
    const int*   dqz = (const int*)  d_in[9];
    float* out = (float*)d_out;

    cudaFuncSetAttribute(gateup_mma, cudaFuncAttributeMaxDynamicSharedMemorySize, GU_SMEM);
    cudaFuncSetAttribute(down_mma,   cudaFuncAttributeMaxDynamicSharedMemorySize, DN_SMEM);

    cvtx_k<<<(int)((size_t)M_TOT * K1 / 8 / 256), 256>>>(x);

    dim3 gridA(N1 / 128, M_TOT / 128);   // 86 x 32
    gateup_mma<<<gridA, NTHREADS, GU_SMEM>>>(gqw, gsc, gqz, uqw, usc, uqz);

    dim3 gridB(N2 / 128, M_TOT / 128);   // 32 x 32
    down_mma<<<gridB, NTHREADS, DN_SMEM>>>(dqw, dsc, dqz, out);
}